// round 12
// baseline (speedup 1.0000x reference)
#include <cuda_runtime.h>
#include <cuda_bf16.h>
#include <cmath>
#include <cstdint>

// Problem constants (fixed by setup_inputs: B=8, L=20*50+1, d_model=1024, H=16, 2 layers)
namespace {
constexpr int B    = 8;
constexpr int L    = 1001;
constexpr int D    = 1024;
constexpr int H    = 16;
constexpr int DK   = 64;
constexpr int NKQ  = 1000;   // query row index
constexpr int KCLS = 50;     // class block size
constexpr int TI   = 64;     // row tile (4 warps x 16)
constexpr int TJ   = 64;     // key tile
constexpr int NT   = (L + TJ - 1) / TJ;   // 16
constexpr int LDS  = 72;     // bf16 elems per smem row (144B stride: conflict-free ldmatrix)
constexpr int TILE = TJ * LDS;            // elems per hi (or lo) tile
constexpr int BUFE = 2 * TILE;            // elems per buffer (hi+lo)
constexpr int SMEM_BYTES = 3 * BUFE * 2;  // 2 K bufs + 1 Q buf = 55296 B (4 CTAs/SM)
// fixed-base softmax: e^(s/8 - 24) = 2^(acc*C1 + C0). Scores are bounded (|s|<~16,
// diag >= 0 so denominator never vanishes); the common e^-24 scale cancels in o/l.
constexpr float C1 = 0.125f * 1.4426950408889634f;
constexpr float C0 = -24.0f * 1.4426950408889634f;
}

// bf16 hi/lo split activations (global scratch; no-alloc rule).
__device__ __nv_bfloat16 g_xh[(size_t)B * L * D];
__device__ __nv_bfloat16 g_xl[(size_t)B * L * D];
__device__ __nv_bfloat16 g_yh[(size_t)B * L * D];
__device__ __nv_bfloat16 g_yl[(size_t)B * L * D];

__device__ __forceinline__ uint32_t smem_u32(const void* p) {
    return (uint32_t)__cvta_generic_to_shared(p);
}
__device__ __forceinline__ void ldmx4(uint32_t a, uint32_t& r0, uint32_t& r1, uint32_t& r2, uint32_t& r3) {
    asm volatile("ldmatrix.sync.aligned.m8n8.x4.shared.b16 {%0,%1,%2,%3},[%4];"
                 : "=r"(r0), "=r"(r1), "=r"(r2), "=r"(r3) : "r"(a));
}
__device__ __forceinline__ void ldmx4t(uint32_t a, uint32_t& r0, uint32_t& r1, uint32_t& r2, uint32_t& r3) {
    asm volatile("ldmatrix.sync.aligned.m8n8.x4.trans.shared.b16 {%0,%1,%2,%3},[%4];"
                 : "=r"(r0), "=r"(r1), "=r"(r2), "=r"(r3) : "r"(a));
}
__device__ __forceinline__ void mma_bf16(float* d, const uint32_t* a, uint32_t b0, uint32_t b1) {
    asm volatile("mma.sync.aligned.m16n8k16.row.col.f32.bf16.bf16.f32 "
                 "{%0,%1,%2,%3},{%4,%5,%6,%7},{%8,%9},{%0,%1,%2,%3};"
                 : "+f"(d[0]), "+f"(d[1]), "+f"(d[2]), "+f"(d[3])
                 : "r"(a[0]), "r"(a[1]), "r"(a[2]), "r"(a[3]), "r"(b0), "r"(b1));
}
__device__ __forceinline__ float ex2(float x) {
    float r; asm("ex2.approx.ftz.f32 %0,%1;" : "=f"(r) : "f"(x)); return r;
}
// Fast 2-term bf16 split of pair (a,b): a -> low halves, b -> high halves.
__device__ __forceinline__ void split2(float a, float b, uint32_t& hi, uint32_t& lo) {
    uint32_t h;
    asm("cvt.rn.bf16x2.f32 %0, %1, %2;" : "=r"(h) : "f"(b), "f"(a));
    const float fa = __uint_as_float(h << 16);
    const float fb = __uint_as_float(h & 0xffff0000u);
    uint32_t l;
    asm("cvt.rn.bf16x2.f32 %0, %1, %2;" : "=r"(l) : "f"(b - fb), "f"(a - fa));
    hi = h; lo = l;
}
__device__ __forceinline__ void cp_commit() { asm volatile("cp.async.commit_group;"); }
template<int N> __device__ __forceinline__ void cp_wait() {
    asm volatile("cp.async.wait_group %0;" :: "n"(N));
}

// Async-stage a 64-row tile (this head's 64 bf16 cols) of hi+lo into smem buffer.
// 1024 16B chunks / 128 threads = 8 per thread. OOB rows zero-filled via src-size=0.
__device__ __forceinline__ void stage_async(const __nv_bfloat16* __restrict__ gh,
                                            const __nv_bfloat16* __restrict__ gl,
                                            int base_row, __nv_bfloat16* sbuf, int tid) {
#pragma unroll
    for (int it = 0; it < 8; ++it) {
        int idx = tid + 128 * it;          // 0..1023
        int arr = idx >> 9;                // 0 = hi, 1 = lo
        int rem = idx & 511;
        int row = rem >> 3;
        int ch  = rem & 7;                 // 16B chunk within 128B row segment
        int g   = base_row + row;
        const __nv_bfloat16* src = (arr ? gl : gh) + (size_t)g * D + ch * 8;
        uint32_t dst = smem_u32(sbuf + arr * TILE + row * LDS + ch * 8);
        int sz = (g < L) ? 16 : 0;
        asm volatile("cp.async.ca.shared.global [%0], [%1], 16, %2;"
                     :: "r"(dst), "l"(src), "r"(sz));
    }
}

// ---- S-half = Q K^T for 32 of the 64 j-columns (bf16x3, unscaled).
// acc[4][4] covers n = half*32 .. half*32+31. Q fragments reloaded per k-chunk. ----
template<int HALF>
__device__ __forceinline__ void s_phase_half(const __nv_bfloat16* kb, const __nv_bfloat16* qb,
                                             int qoff, float (&acc)[4][4], int lrK, int lcK) {
#pragma unroll
    for (int nt = 0; nt < 4; ++nt)
#pragma unroll
        for (int v = 0; v < 4; ++v) acc[nt][v] = 0.f;
#pragma unroll
    for (int kc = 0; kc < 4; ++kc) {
        uint32_t qh[4], ql[4];
        ldmx4(smem_u32(qb + qoff + kc * 16),        qh[0], qh[1], qh[2], qh[3]);
        ldmx4(smem_u32(qb + TILE + qoff + kc * 16), ql[0], ql[1], ql[2], ql[3]);
#pragma unroll
        for (int np = 0; np < 2; ++np) {
            const int ntp = 2 * HALF + np;
            const int off = (16 * ntp + lrK) * LDS + kc * 16 + lcK;
            uint32_t bh0, bh1, bh2, bh3, bl0, bl1, bl2, bl3;
            ldmx4(smem_u32(kb + off),        bh0, bh1, bh2, bh3);
            ldmx4(smem_u32(kb + TILE + off), bl0, bl1, bl2, bl3);
            mma_bf16(acc[2 * np],     qh, bh0, bh1);
            mma_bf16(acc[2 * np],     qh, bl0, bl1);
            mma_bf16(acc[2 * np],     ql, bh0, bh1);
            mma_bf16(acc[2 * np + 1], qh, bh2, bh3);
            mma_bf16(acc[2 * np + 1], qh, bl2, bl3);
            mma_bf16(acc[2 * np + 1], ql, bh2, bh3);
        }
    }
}

// ---- O += P_half V_half (contraction over 32 j's; V = K tile, trans ldmatrix) ----
template<int HALF>
__device__ __forceinline__ void pv_phase_half(const __nv_bfloat16* kb,
                                              const uint32_t (&ah)[2][4], const uint32_t (&al)[2][4],
                                              float (&o)[8][4], int lrA, int lcA) {
#pragma unroll
    for (int kj = 0; kj < 2; ++kj) {
        const int kcj = 2 * HALF + kj;
#pragma unroll
        for (int ntp = 0; ntp < 4; ++ntp) {
            const int off = (kcj * 16 + lrA) * LDS + 16 * ntp + lcA;
            uint32_t vh0, vh1, vh2, vh3, vl0, vl1, vl2, vl3;
            ldmx4t(smem_u32(kb + off),        vh0, vh1, vh2, vh3);
            ldmx4t(smem_u32(kb + TILE + off), vl0, vl1, vl2, vl3);
            mma_bf16(o[2 * ntp],     ah[kj], vh0, vh1);
            mma_bf16(o[2 * ntp],     ah[kj], vl0, vl1);
            mma_bf16(o[2 * ntp],     al[kj], vh0, vh1);
            mma_bf16(o[2 * ntp + 1], ah[kj], vh2, vh3);
            mma_bf16(o[2 * ntp + 1], ah[kj], vl2, vl3);
            mma_bf16(o[2 * ntp + 1], al[kj], vh2, vh3);
        }
    }
}

// Softmax + structured multiplier + pack P half into A-fragments (j covers 32 cols).
// wr* = {w_in_class, w_out_class, w_diag, w_querycol} per owned row.
template<bool MASK>
__device__ __forceinline__ void softmax_pack_half(const float (&acc)[4][4], int jb,
                                                  int gi0, int gi1, int jlo0, int jlo1,
                                                  const float* wr0, const float* wr1,
                                                  uint32_t (&ah)[2][4], uint32_t (&al)[2][4],
                                                  float& l0, float& l1, int lane)
{
#pragma unroll
    for (int nt = 0; nt < 4; ++nt) {
        const int gj0 = jb + nt * 8 + (lane & 3) * 2;
        const int gj1 = gj0 + 1;
        float e00 = ex2(fmaf(acc[nt][0], C1, C0));
        float e01 = ex2(fmaf(acc[nt][1], C1, C0));
        float e10 = ex2(fmaf(acc[nt][2], C1, C0));
        float e11 = ex2(fmaf(acc[nt][3], C1, C0));
        if (MASK) {
            if (gj0 >= L) { e00 = 0.f; e10 = 0.f; }
            if (gj1 >= L) { e01 = 0.f; e11 = 0.f; }
        }
        l0 += e00 + e01;
        l1 += e10 + e11;
        float t00 = ((unsigned)(gj0 - jlo0) < (unsigned)KCLS) ? wr0[0] : wr0[1];
        float t01 = ((unsigned)(gj1 - jlo0) < (unsigned)KCLS) ? wr0[0] : wr0[1];
        float t10 = ((unsigned)(gj0 - jlo1) < (unsigned)KCLS) ? wr1[0] : wr1[1];
        float t11 = ((unsigned)(gj1 - jlo1) < (unsigned)KCLS) ? wr1[0] : wr1[1];
        if (gj0 == gi0) t00 = wr0[2];
        if (gj1 == gi0) t01 = wr0[2];
        if (gj0 == gi1) t10 = wr1[2];
        if (gj1 == gi1) t11 = wr1[2];
        if (gj0 == NKQ) { t00 = wr0[3]; t10 = wr1[3]; }
        if (gj1 == NKQ) { t01 = wr0[3]; t11 = wr1[3]; }
        const int kj = nt >> 1, of = (nt & 1) * 2;
        split2(e00 * t00, e01 * t01, ah[kj][of],     al[kj][of]);
        split2(e10 * t10, e11 * t11, ah[kj][of + 1], al[kj][of + 1]);
    }
}

// Initial fp32 -> bf16 hi/lo split (one-time).
__global__ void convert_split(const float* __restrict__ x,
                              __nv_bfloat16* __restrict__ xh,
                              __nv_bfloat16* __restrict__ xl) {
    size_t i = ((size_t)blockIdx.x * blockDim.x + threadIdx.x) * 4;
    float4 v = *reinterpret_cast<const float4*>(x + i);
    uint32_t h0, l0, h1, l1;
    split2(v.x, v.y, h0, l0);
    split2(v.z, v.w, h1, l1);
    *reinterpret_cast<uint2*>(xh + i) = make_uint2(h0, h1);
    *reinterpret_cast<uint2*>(xl + i) = make_uint2(l0, l1);
}

template<bool SPLIT_OUT>
__global__ void __launch_bounds__(128, 4)
encoder_layer_tc(const __nv_bfloat16* __restrict__ xh,
                 const __nv_bfloat16* __restrict__ xl,
                 const float* __restrict__ w6,        // [H][6] for this layer
                 __nv_bfloat16* __restrict__ yh,      // SPLIT_OUT
                 __nv_bfloat16* __restrict__ yl,      // SPLIT_OUT
                 float* __restrict__ yo)              // !SPLIT_OUT
{
    extern __shared__ __nv_bfloat16 sbuf[];     // [K0][K1][Q] hi+lo buffers

    const int tid  = threadIdx.x;
    const int w    = tid >> 5;
    const int lane = tid & 31;
    const int h    = blockIdx.y & (H - 1);
    const int b    = blockIdx.y >> 4;
    const int i_base = blockIdx.x * TI;

    const size_t slice = (size_t)b * L * D + h * DK;
    const __nv_bfloat16* xhb = xh + slice;
    const __nv_bfloat16* xlb = xl + slice;
    __nv_bfloat16* qb = sbuf + 2 * BUFE;        // resident Q buffer

    float t6[6];
#pragma unroll
    for (int q = 0; q < 6; ++q) t6[q] = tanhf(w6[h * 6 + q]);

    // lane-derived ldmatrix offset pieces
    const int lrA = (lane & 7) + ((lane >> 3) & 1) * 8;  // A / trans-B row part
    const int lcA = ((lane >> 4) & 1) * 8;               // A / trans-B col part
    const int lrK = (lane & 7) + ((lane >> 4) & 1) * 8;  // non-trans B row part
    const int lcK = ((lane >> 3) & 1) * 8;               // non-trans B col part
    const int qoff = (w * 16 + lrA) * LDS + lcA;         // per-tile Q fragment base

    // prologue: Q -> qb, K0 -> buf0, K1 -> buf1 (separate groups)
    stage_async(xhb, xlb, i_base, qb,          tid); cp_commit();
    stage_async(xhb, xlb, 0,      sbuf,        tid); cp_commit();
    stage_async(xhb, xlb, TJ,     sbuf + BUFE, tid); cp_commit();

    float o[8][4];
#pragma unroll
    for (int nt = 0; nt < 8; ++nt)
#pragma unroll
        for (int v = 0; v < 4; ++v) o[nt][v] = 0.f;
    float l0 = 0.f, l1 = 0.f;

    const int gi0 = i_base + w * 16 + (lane >> 2);
    const int gi1 = gi0 + 8;
    const int jlo0 = (gi0 / KCLS) * KCLS;
    const int jlo1 = (gi1 / KCLS) * KCLS;
    // per-row weight quadruple {in_class, out_class, diag, query_col};
    // query row (gi==NKQ): everything t6[4] except col NKQ -> t6[5]
    float wr0[4], wr1[4];
    if (gi0 == NKQ) { wr0[0] = wr0[1] = t6[4]; wr0[2] = wr0[3] = t6[5]; }
    else            { wr0[0] = t6[1]; wr0[1] = t6[2]; wr0[2] = t6[0]; wr0[3] = t6[3]; }
    if (gi1 == NKQ) { wr1[0] = wr1[1] = t6[4]; wr1[2] = wr1[3] = t6[5]; }
    else            { wr1[0] = t6[1]; wr1[1] = t6[2]; wr1[2] = t6[0]; wr1[3] = t6[3]; }

    for (int jt = 0; jt < NT; ++jt) {
        const __nv_bfloat16* kb = sbuf + (jt & 1) * BUFE;   // K(jt)

        cp_wait<1>();        // Q, K0..K(jt) landed; K(jt+1) may be in flight
        __syncthreads();

        // ---- half 0: j = jt*64 .. +31 (never masked: last tile half0 ends at 991 < L) ----
        {
            float acc[4][4];
            s_phase_half<0>(kb, qb, qoff, acc, lrK, lcK);
            uint32_t ah[2][4], al[2][4];
            softmax_pack_half<false>(acc, jt * TJ, gi0, gi1, jlo0, jlo1,
                                     wr0, wr1, ah, al, l0, l1, lane);
            pv_phase_half<0>(kb, ah, al, o, lrA, lcA);
        }
        // ---- half 1: j = jt*64+32 .. +63 (masked only on the last tile) ----
        {
            float acc[4][4];
            s_phase_half<1>(kb, qb, qoff, acc, lrK, lcK);
            uint32_t ah[2][4], al[2][4];
            if (jt == NT - 1)
                softmax_pack_half<true >(acc, jt * TJ + 32, gi0, gi1, jlo0, jlo1,
                                         wr0, wr1, ah, al, l0, l1, lane);
            else
                softmax_pack_half<false>(acc, jt * TJ + 32, gi0, gi1, jlo0, jlo1,
                                         wr0, wr1, ah, al, l0, l1, lane);
            pv_phase_half<1>(kb, ah, al, o, lrA, lcA);
        }

        __syncthreads();     // all warps done reading kb before restaging it
        if (jt + 2 < NT)
            stage_async(xhb, xlb, (jt + 2) * TJ, sbuf + (jt & 1) * BUFE, tid);
        cp_commit();         // always commit (possibly empty) to keep wait bookkeeping exact
    }

    // ---- epilogue: reduce denominators once, divide, write ----
    l0 += __shfl_xor_sync(0xffffffffu, l0, 1);
    l0 += __shfl_xor_sync(0xffffffffu, l0, 2);
    l1 += __shfl_xor_sync(0xffffffffu, l1, 1);
    l1 += __shfl_xor_sync(0xffffffffu, l1, 2);
    const float inv0 = 1.f / l0, inv1 = 1.f / l1;

#pragma unroll
    for (int nt = 0; nt < 8; ++nt) {
        const int c = nt * 8 + (lane & 3) * 2;
        if (SPLIT_OUT) {
            if (gi0 < L) {
                uint32_t hi, lo;
                split2(o[nt][0] * inv0, o[nt][1] * inv0, hi, lo);
                *reinterpret_cast<uint32_t*>(yh + slice + (size_t)gi0 * D + c) = hi;
                *reinterpret_cast<uint32_t*>(yl + slice + (size_t)gi0 * D + c) = lo;
            }
            if (gi1 < L) {
                uint32_t hi, lo;
                split2(o[nt][2] * inv1, o[nt][3] * inv1, hi, lo);
                *reinterpret_cast<uint32_t*>(yh + slice + (size_t)gi1 * D + c) = hi;
                *reinterpret_cast<uint32_t*>(yl + slice + (size_t)gi1 * D + c) = lo;
            }
        } else {
            if (gi0 < L)
                *reinterpret_cast<float2*>(yo + slice + (size_t)gi0 * D + c) =
                    make_float2(o[nt][0] * inv0, o[nt][1] * inv0);
            if (gi1 < L)
                *reinterpret_cast<float2*>(yo + slice + (size_t)gi1 * D + c) =
                    make_float2(o[nt][2] * inv1, o[nt][3] * inv1);
        }
    }
}

extern "C" void kernel_launch(void* const* d_in, const int* in_sizes, int n_in,
                              void* d_out, int out_size)
{
    const float* samples = (const float*)d_in[0];   // [B, L, D] fp32
    const float* weights = (const float*)d_in[1];   // [2, H, 6] fp32
    float* out = (float*)d_out;                     // [B, L, D] fp32

    __nv_bfloat16 *xh, *xl, *yh, *yl;
    cudaGetSymbolAddress((void**)&xh, g_xh);
    cudaGetSymbolAddress((void**)&xl, g_xl);
    cudaGetSymbolAddress((void**)&yh, g_yh);
    cudaGetSymbolAddress((void**)&yl, g_yl);

    cudaFuncSetAttribute(encoder_layer_tc<true >,
                         cudaFuncAttributeMaxDynamicSharedMemorySize, SMEM_BYTES);
    cudaFuncSetAttribute(encoder_layer_tc<false>,
                         cudaFuncAttributeMaxDynamicSharedMemorySize, SMEM_BYTES);

    const int total4 = B * L * D / 4;               // exactly divisible
    convert_split<<<total4 / 256, 256>>>(samples, xh, xl);

    dim3 grid(NT, B * H);                           // 16 x 128
    encoder_layer_tc<true ><<<grid, 128, SMEM_BYTES>>>(xh, xl, weights,          yh, yl, nullptr);
    encoder_layer_tc<false><<<grid, 128, SMEM_BYTES>>>(yh, yl, weights + H * 6, nullptr, nullptr, out);
}

// round 14
// speedup vs baseline: 1.1785x; 1.1785x over previous
#include <cuda_runtime.h>
#include <cuda_bf16.h>
#include <cuda_fp16.h>
#include <cmath>
#include <cstdint>

// Problem constants (fixed by setup_inputs: B=8, L=20*50+1, d_model=1024, H=16, 2 layers)
namespace {
constexpr int B    = 8;
constexpr int L    = 1001;
constexpr int D    = 1024;
constexpr int H    = 16;
constexpr int DK   = 64;
constexpr int NKQ  = 1000;   // query row index
constexpr int KCLS = 50;     // class block size
constexpr int TI   = 64;     // row tile (4 warps x 16)
constexpr int TJ   = 64;     // key tile
constexpr int NT   = (L + TJ - 1) / TJ;   // 16
constexpr int LDS  = 72;     // elems per smem row (144B stride: conflict-free ldmatrix)
constexpr int TILE = TJ * LDS;            // elems per tile plane
constexpr int KB3  = 3 * TILE;            // K buffer: [f16 | bf16hi | bf16lo]
constexpr int SMEM_BYTES = (2 * KB3 + TILE) * 2;  // 2 K bufs + 1 fp16 Q = 64512 B
// fixed-base softmax: e^(s/8 - 24) = 2^(acc*C1 + C0). Scores are bounded (|s|<~16·8,
// diag >= 0 so denominator never vanishes); the common e^-24 scale cancels in o/l.
constexpr float C1 = 0.125f * 1.4426950408889634f;
constexpr float C0 = -24.0f * 1.4426950408889634f;
}

// activations in three representations (global scratch; no-alloc rule):
// fp16 (S-GEMM operands) + bf16 hi/lo (PV operands, 2^-18 exact).
__device__ __half        g_x16[(size_t)B * L * D];
__device__ __nv_bfloat16 g_xh [(size_t)B * L * D];
__device__ __nv_bfloat16 g_xl [(size_t)B * L * D];
__device__ __half        g_y16[(size_t)B * L * D];
__device__ __nv_bfloat16 g_yh [(size_t)B * L * D];
__device__ __nv_bfloat16 g_yl [(size_t)B * L * D];

__device__ __forceinline__ uint32_t smem_u32(const void* p) {
    return (uint32_t)__cvta_generic_to_shared(p);
}
__device__ __forceinline__ void ldmx4(uint32_t a, uint32_t& r0, uint32_t& r1, uint32_t& r2, uint32_t& r3) {
    asm volatile("ldmatrix.sync.aligned.m8n8.x4.shared.b16 {%0,%1,%2,%3},[%4];"
                 : "=r"(r0), "=r"(r1), "=r"(r2), "=r"(r3) : "r"(a));
}
__device__ __forceinline__ void ldmx4t(uint32_t a, uint32_t& r0, uint32_t& r1, uint32_t& r2, uint32_t& r3) {
    asm volatile("ldmatrix.sync.aligned.m8n8.x4.trans.shared.b16 {%0,%1,%2,%3},[%4];"
                 : "=r"(r0), "=r"(r1), "=r"(r2), "=r"(r3) : "r"(a));
}
__device__ __forceinline__ void mma_bf16(float* d, const uint32_t* a, uint32_t b0, uint32_t b1) {
    asm volatile("mma.sync.aligned.m16n8k16.row.col.f32.bf16.bf16.f32 "
                 "{%0,%1,%2,%3},{%4,%5,%6,%7},{%8,%9},{%0,%1,%2,%3};"
                 : "+f"(d[0]), "+f"(d[1]), "+f"(d[2]), "+f"(d[3])
                 : "r"(a[0]), "r"(a[1]), "r"(a[2]), "r"(a[3]), "r"(b0), "r"(b1));
}
__device__ __forceinline__ void mma_f16(float* d, const uint32_t* a, uint32_t b0, uint32_t b1) {
    asm volatile("mma.sync.aligned.m16n8k16.row.col.f32.f16.f16.f32 "
                 "{%0,%1,%2,%3},{%4,%5,%6,%7},{%8,%9},{%0,%1,%2,%3};"
                 : "+f"(d[0]), "+f"(d[1]), "+f"(d[2]), "+f"(d[3])
                 : "r"(a[0]), "r"(a[1]), "r"(a[2]), "r"(a[3]), "r"(b0), "r"(b1));
}
__device__ __forceinline__ float ex2(float x) {
    float r; asm("ex2.approx.ftz.f32 %0,%1;" : "=f"(r) : "f"(x)); return r;
}
// Fast 2-term bf16 split of pair (a,b): a -> low halves, b -> high halves.
__device__ __forceinline__ void split2(float a, float b, uint32_t& hi, uint32_t& lo) {
    uint32_t h;
    asm("cvt.rn.bf16x2.f32 %0, %1, %2;" : "=r"(h) : "f"(b), "f"(a));
    const float fa = __uint_as_float(h << 16);
    const float fb = __uint_as_float(h & 0xffff0000u);
    uint32_t l;
    asm("cvt.rn.bf16x2.f32 %0, %1, %2;" : "=r"(l) : "f"(b - fb), "f"(a - fa));
    hi = h; lo = l;
}
__device__ __forceinline__ void cp_commit() { asm volatile("cp.async.commit_group;"); }
template<int N> __device__ __forceinline__ void cp_wait() {
    asm volatile("cp.async.wait_group %0;" :: "n"(N));
}

// Async-stage a K tile: [fp16 | bf16hi | bf16lo] planes (64 rows x this head's 64 cols).
// 1536 16B chunks / 128 threads = 12 per thread. OOB rows zero-filled via src-size=0.
__device__ __forceinline__ void stage_k(const __half* __restrict__ g16,
                                        const __nv_bfloat16* __restrict__ gh,
                                        const __nv_bfloat16* __restrict__ gl,
                                        int base_row, __nv_bfloat16* sbuf, int tid) {
#pragma unroll
    for (int it = 0; it < 12; ++it) {
        int idx = tid + 128 * it;          // 0..1535
        int arr = idx >> 9;                // 0 = f16, 1 = bf16hi, 2 = bf16lo
        int rem = idx & 511;
        int row = rem >> 3;
        int ch  = rem & 7;                 // 16B chunk within 128B row segment
        int g   = base_row + row;
        const __nv_bfloat16* base = (arr == 0) ? (const __nv_bfloat16*)g16
                                  : (arr == 1) ? gh : gl;
        const void* src = base + (size_t)g * D + ch * 8;
        uint32_t dst = smem_u32(sbuf + arr * TILE + row * LDS + ch * 8);
        int sz = (g < L) ? 16 : 0;
        asm volatile("cp.async.ca.shared.global [%0], [%1], 16, %2;"
                     :: "r"(dst), "l"(src), "r"(sz));
    }
}
// Async-stage the fp16 Q tile (512 chunks / 128 threads = 4 per thread).
__device__ __forceinline__ void stage_q(const __half* __restrict__ g16,
                                        int base_row, __nv_bfloat16* qb, int tid) {
#pragma unroll
    for (int it = 0; it < 4; ++it) {
        int idx = tid + 128 * it;          // 0..511
        int row = idx >> 3;
        int ch  = idx & 7;
        int g   = base_row + row;
        const void* src = g16 + (size_t)g * D + ch * 8;
        uint32_t dst = smem_u32(qb + row * LDS + ch * 8);
        int sz = (g < L) ? 16 : 0;
        asm volatile("cp.async.ca.shared.global [%0], [%1], 16, %2;"
                     :: "r"(dst), "l"(src), "r"(sz));
    }
}

// ---- S = fl16(Q) fl16(K)^T : single-term fp16 GEMM (32 MMAs/warp-tile) ----
__device__ __forceinline__ void s_phase(const __nv_bfloat16* kb, const uint32_t (&qf)[4][4],
                                        float (&acc)[8][4], int lrK, int lcK) {
#pragma unroll
    for (int nt = 0; nt < 8; ++nt)
#pragma unroll
        for (int v = 0; v < 4; ++v) acc[nt][v] = 0.f;
#pragma unroll
    for (int kc = 0; kc < 4; ++kc) {
#pragma unroll
        for (int ntp = 0; ntp < 4; ++ntp) {
            const int off = (16 * ntp + lrK) * LDS + kc * 16 + lcK;
            uint32_t b0, b1, b2, b3;
            ldmx4(smem_u32(kb + off), b0, b1, b2, b3);
            mma_f16(acc[2 * ntp],     qf[kc], b0, b1);
            mma_f16(acc[2 * ntp + 1], qf[kc], b2, b3);
        }
    }
}

// ---- O += P V : bf16x3 (V = K tile bf16 planes, trans ldmatrix) ----
__device__ __forceinline__ void pv_phase(const __nv_bfloat16* kb,
                                         const uint32_t (&ah)[4][4], const uint32_t (&al)[4][4],
                                         float (&o)[8][4], int lrA, int lcA) {
    const __nv_bfloat16* vh = kb + TILE;       // bf16 hi plane
    const __nv_bfloat16* vl = kb + 2 * TILE;   // bf16 lo plane
#pragma unroll
    for (int kc = 0; kc < 4; ++kc) {
#pragma unroll
        for (int ntp = 0; ntp < 4; ++ntp) {
            const int off = (kc * 16 + lrA) * LDS + 16 * ntp + lcA;
            uint32_t vh0, vh1, vh2, vh3, vl0, vl1, vl2, vl3;
            ldmx4t(smem_u32(vh + off), vh0, vh1, vh2, vh3);
            ldmx4t(smem_u32(vl + off), vl0, vl1, vl2, vl3);
            mma_bf16(o[2 * ntp],     ah[kc], vh0, vh1);
            mma_bf16(o[2 * ntp],     ah[kc], vl0, vl1);
            mma_bf16(o[2 * ntp],     al[kc], vh0, vh1);
            mma_bf16(o[2 * ntp + 1], ah[kc], vh2, vh3);
            mma_bf16(o[2 * ntp + 1], ah[kc], vl2, vl3);
            mma_bf16(o[2 * ntp + 1], al[kc], vh2, vh3);
        }
    }
}

// Softmax + structured multiplier + pack P into A-fragments.
// DIAG: override the MMA score with the exact fp32 self-dot on the diagonal
// (kills the dominant fp16 truncation error where softmax mass concentrates).
template<bool MASK, bool DIAG>
__device__ __forceinline__ void softmax_pack(const float (&acc)[8][4], int j_base,
                                             int gi0, int gi1, int jlo0, int jlo1,
                                             float nd0, float nd1,
                                             const float* wr0, const float* wr1,
                                             uint32_t (&ah)[4][4], uint32_t (&al)[4][4],
                                             float& l0, float& l1, int lane)
{
#pragma unroll
    for (int nt = 0; nt < 8; ++nt) {
        const int gj0 = j_base + nt * 8 + (lane & 3) * 2;
        const int gj1 = gj0 + 1;
        float a00 = acc[nt][0], a01 = acc[nt][1], a10 = acc[nt][2], a11 = acc[nt][3];
        if (DIAG) {
            if (gj0 == gi0) a00 = nd0;
            if (gj1 == gi0) a01 = nd0;
            if (gj0 == gi1) a10 = nd1;
            if (gj1 == gi1) a11 = nd1;
        }
        float e00 = ex2(fmaf(a00, C1, C0));
        float e01 = ex2(fmaf(a01, C1, C0));
        float e10 = ex2(fmaf(a10, C1, C0));
        float e11 = ex2(fmaf(a11, C1, C0));
        if (MASK) {
            if (gj0 >= L) { e00 = 0.f; e10 = 0.f; }
            if (gj1 >= L) { e01 = 0.f; e11 = 0.f; }
        }
        l0 += e00 + e01;
        l1 += e10 + e11;
        float t00 = ((unsigned)(gj0 - jlo0) < (unsigned)KCLS) ? wr0[0] : wr0[1];
        float t01 = ((unsigned)(gj1 - jlo0) < (unsigned)KCLS) ? wr0[0] : wr0[1];
        float t10 = ((unsigned)(gj0 - jlo1) < (unsigned)KCLS) ? wr1[0] : wr1[1];
        float t11 = ((unsigned)(gj1 - jlo1) < (unsigned)KCLS) ? wr1[0] : wr1[1];
        if (gj0 == gi0) t00 = wr0[2];
        if (gj1 == gi0) t01 = wr0[2];
        if (gj0 == gi1) t10 = wr1[2];
        if (gj1 == gi1) t11 = wr1[2];
        if (gj0 == NKQ) { t00 = wr0[3]; t10 = wr1[3]; }
        if (gj1 == NKQ) { t01 = wr0[3]; t11 = wr1[3]; }
        const int kc = nt >> 1, of = (nt & 1) * 2;
        split2(e00 * t00, e01 * t01, ah[kc][of],     al[kc][of]);
        split2(e10 * t10, e11 * t11, ah[kc][of + 1], al[kc][of + 1]);
    }
}

// exact fp32 row self-dot: 16 cols starting at part*16 of (xh+xl)
__device__ __forceinline__ float ndot_part(const __nv_bfloat16* rh, const __nv_bfloat16* rl,
                                           int part) {
    const uint4* ph = reinterpret_cast<const uint4*>(rh + part * 16);
    const uint4* pl = reinterpret_cast<const uint4*>(rl + part * 16);
    float s = 0.f;
#pragma unroll
    for (int q = 0; q < 2; ++q) {
        uint4 hw = ph[q], lw = pl[q];
        const uint32_t hv[4] = {hw.x, hw.y, hw.z, hw.w};
        const uint32_t lv[4] = {lw.x, lw.y, lw.z, lw.w};
#pragma unroll
        for (int i = 0; i < 4; ++i) {
            __nv_bfloat162 h2 = *reinterpret_cast<const __nv_bfloat162*>(&hv[i]);
            __nv_bfloat162 l2 = *reinterpret_cast<const __nv_bfloat162*>(&lv[i]);
            float v0 = __bfloat162float(h2.x) + __bfloat162float(l2.x);
            float v1 = __bfloat162float(h2.y) + __bfloat162float(l2.y);
            s = fmaf(v0, v0, s);
            s = fmaf(v1, v1, s);
        }
    }
    return s;
}

// Initial fp32 -> {fp16, bf16 hi, bf16 lo} (one-time).
__global__ void convert_split(const float* __restrict__ x,
                              __half* __restrict__ x16,
                              __nv_bfloat16* __restrict__ xh,
                              __nv_bfloat16* __restrict__ xl) {
    size_t i = ((size_t)blockIdx.x * blockDim.x + threadIdx.x) * 4;
    float4 v = *reinterpret_cast<const float4*>(x + i);
    uint32_t h0, l0, h1, l1;
    split2(v.x, v.y, h0, l0);
    split2(v.z, v.w, h1, l1);
    *reinterpret_cast<uint2*>(xh + i) = make_uint2(h0, h1);
    *reinterpret_cast<uint2*>(xl + i) = make_uint2(l0, l1);
    __half2 f0 = __floats2half2_rn(v.x, v.y);
    __half2 f1 = __floats2half2_rn(v.z, v.w);
    *reinterpret_cast<__half2*>(x16 + i)     = f0;
    *reinterpret_cast<__half2*>(x16 + i + 2) = f1;
}

template<bool SPLIT_OUT>
__global__ void __launch_bounds__(128, 3)
encoder_layer_tc(const __half* __restrict__ x16,
                 const __nv_bfloat16* __restrict__ xh,
                 const __nv_bfloat16* __restrict__ xl,
                 const float* __restrict__ w6,        // [H][6] for this layer
                 __half* __restrict__ y16,            // SPLIT_OUT
                 __nv_bfloat16* __restrict__ yh,      // SPLIT_OUT
                 __nv_bfloat16* __restrict__ yl,      // SPLIT_OUT
                 float* __restrict__ yo)              // !SPLIT_OUT
{
    extern __shared__ __nv_bfloat16 sbuf[];     // [K0(3T)][K1(3T)][Q(1T)]

    const int tid  = threadIdx.x;
    const int w    = tid >> 5;
    const int lane = tid & 31;
    const int h    = blockIdx.y & (H - 1);
    const int b    = blockIdx.y >> 4;
    const int i_base = blockIdx.x * TI;

    const size_t slice = (size_t)b * L * D + h * DK;
    const __half*        x16b = x16 + slice;
    const __nv_bfloat16* xhb  = xh + slice;
    const __nv_bfloat16* xlb  = xl + slice;
    __nv_bfloat16* qb = sbuf + 2 * KB3;         // resident fp16 Q buffer

    float t6[6];
#pragma unroll
    for (int q = 0; q < 6; ++q) t6[q] = tanhf(w6[h * 6 + q]);

    // lane-derived ldmatrix offset pieces
    const int lrA = (lane & 7) + ((lane >> 3) & 1) * 8;  // A / trans-B row part
    const int lcA = ((lane >> 4) & 1) * 8;               // A / trans-B col part
    const int lrK = (lane & 7) + ((lane >> 4) & 1) * 8;  // non-trans B row part
    const int lcK = ((lane >> 3) & 1) * 8;               // non-trans B col part

    // prologue: Q -> qb, K0 -> buf0, K1 -> buf1 (separate groups)
    stage_q(x16b, i_base, qb, tid);                     cp_commit();
    stage_k(x16b, xhb, xlb, 0,  sbuf,       tid);       cp_commit();
    stage_k(x16b, xhb, xlb, TJ, sbuf + KB3, tid);       cp_commit();

    const int gi0 = i_base + w * 16 + (lane >> 2);
    const int gi1 = gi0 + 8;
    const int jlo0 = (gi0 / KCLS) * KCLS;
    const int jlo1 = (gi1 / KCLS) * KCLS;
    float wr0[4], wr1[4];
    if (gi0 == NKQ) { wr0[0] = wr0[1] = t6[4]; wr0[2] = wr0[3] = t6[5]; }
    else            { wr0[0] = t6[1]; wr0[1] = t6[2]; wr0[2] = t6[0]; wr0[3] = t6[3]; }
    if (gi1 == NKQ) { wr1[0] = wr1[1] = t6[4]; wr1[2] = wr1[3] = t6[5]; }
    else            { wr1[0] = t6[1]; wr1[1] = t6[2]; wr1[2] = t6[0]; wr1[3] = t6[3]; }

    // exact diag scores (fp32 self-dot of xh+xl); quad lanes split 16 cols each
    float nd0 = 0.f, nd1 = 0.f;
    {
        const int part = lane & 3;
        if (gi0 < L) nd0 = ndot_part(xhb + (size_t)gi0 * D, xlb + (size_t)gi0 * D, part);
        if (gi1 < L) nd1 = ndot_part(xhb + (size_t)gi1 * D, xlb + (size_t)gi1 * D, part);
        nd0 += __shfl_xor_sync(0xffffffffu, nd0, 1);
        nd0 += __shfl_xor_sync(0xffffffffu, nd0, 2);
        nd1 += __shfl_xor_sync(0xffffffffu, nd1, 1);
        nd1 += __shfl_xor_sync(0xffffffffu, nd1, 2);
    }

    cp_wait<2>();            // Q landed
    __syncthreads();

    // hoist fp16 Q A-fragments (16 regs)
    uint32_t qf[4][4];
#pragma unroll
    for (int kc = 0; kc < 4; ++kc) {
        const int off = (w * 16 + lrA) * LDS + kc * 16 + lcA;
        ldmx4(smem_u32(qb + off), qf[kc][0], qf[kc][1], qf[kc][2], qf[kc][3]);
    }

    float o[8][4];
#pragma unroll
    for (int nt = 0; nt < 8; ++nt)
#pragma unroll
        for (int v = 0; v < 4; ++v) o[nt][v] = 0.f;
    float l0 = 0.f, l1 = 0.f;

    const int diag_jt = blockIdx.x;     // TI == TJ: the diagonal falls in this j-tile

    for (int jt = 0; jt < NT; ++jt) {
        const __nv_bfloat16* kb = sbuf + (jt & 1) * KB3;   // K(jt)

        cp_wait<1>();        // K(jt) landed; K(jt+1) may be in flight
        __syncthreads();

        float acc[8][4];
        s_phase(kb, qf, acc, lrK, lcK);

        uint32_t ah[4][4], al[4][4];
        if (jt == NT - 1) {
            if (jt == diag_jt)
                softmax_pack<true , true >(acc, jt * TJ, gi0, gi1, jlo0, jlo1, nd0, nd1,
                                           wr0, wr1, ah, al, l0, l1, lane);
            else
                softmax_pack<true , false>(acc, jt * TJ, gi0, gi1, jlo0, jlo1, nd0, nd1,
                                           wr0, wr1, ah, al, l0, l1, lane);
        } else {
            if (jt == diag_jt)
                softmax_pack<false, true >(acc, jt * TJ, gi0, gi1, jlo0, jlo1, nd0, nd1,
                                           wr0, wr1, ah, al, l0, l1, lane);
            else
                softmax_pack<false, false>(acc, jt * TJ, gi0, gi1, jlo0, jlo1, nd0, nd1,
                                           wr0, wr1, ah, al, l0, l1, lane);
        }

        pv_phase(kb, ah, al, o, lrA, lcA);

        __syncthreads();     // all warps done reading kb before restaging it
        if (jt + 2 < NT)
            stage_k(x16b, xhb, xlb, (jt + 2) * TJ, sbuf + (jt & 1) * KB3, tid);
        cp_commit();         // always commit (possibly empty) to keep wait bookkeeping exact
    }

    // ---- epilogue: reduce denominators once, divide, write ----
    l0 += __shfl_xor_sync(0xffffffffu, l0, 1);
    l0 += __shfl_xor_sync(0xffffffffu, l0, 2);
    l1 += __shfl_xor_sync(0xffffffffu, l1, 1);
    l1 += __shfl_xor_sync(0xffffffffu, l1, 2);
    const float inv0 = 1.f / l0, inv1 = 1.f / l1;

#pragma unroll
    for (int nt = 0; nt < 8; ++nt) {
        const int c = nt * 8 + (lane & 3) * 2;
        if (SPLIT_OUT) {
            if (gi0 < L) {
                const float o0 = o[nt][0] * inv0, o1 = o[nt][1] * inv0;
                uint32_t hi, lo;
                split2(o0, o1, hi, lo);
                *reinterpret_cast<uint32_t*>(yh + slice + (size_t)gi0 * D + c) = hi;
                *reinterpret_cast<uint32_t*>(yl + slice + (size_t)gi0 * D + c) = lo;
                *reinterpret_cast<__half2*>(y16 + slice + (size_t)gi0 * D + c) =
                    __floats2half2_rn(o0, o1);
            }
            if (gi1 < L) {
                const float o0 = o[nt][2] * inv1, o1 = o[nt][3] * inv1;
                uint32_t hi, lo;
                split2(o0, o1, hi, lo);
                *reinterpret_cast<uint32_t*>(yh + slice + (size_t)gi1 * D + c) = hi;
                *reinterpret_cast<uint32_t*>(yl + slice + (size_t)gi1 * D + c) = lo;
                *reinterpret_cast<__half2*>(y16 + slice + (size_t)gi1 * D + c) =
                    __floats2half2_rn(o0, o1);
            }
        } else {
            if (gi0 < L)
                *reinterpret_cast<float2*>(yo + slice + (size_t)gi0 * D + c) =
                    make_float2(o[nt][0] * inv0, o[nt][1] * inv0);
            if (gi1 < L)
                *reinterpret_cast<float2*>(yo + slice + (size_t)gi1 * D + c) =
                    make_float2(o[nt][2] * inv1, o[nt][3] * inv1);
        }
    }
}

extern "C" void kernel_launch(void* const* d_in, const int* in_sizes, int n_in,
                              void* d_out, int out_size)
{
    const float* samples = (const float*)d_in[0];   // [B, L, D] fp32
    const float* weights = (const float*)d_in[1];   // [2, H, 6] fp32
    float* out = (float*)d_out;                     // [B, L, D] fp32

    __half *x16, *y16;
    __nv_bfloat16 *xh, *xl, *yh, *yl;
    cudaGetSymbolAddress((void**)&x16, g_x16);
    cudaGetSymbolAddress((void**)&xh,  g_xh);
    cudaGetSymbolAddress((void**)&xl,  g_xl);
    cudaGetSymbolAddress((void**)&y16, g_y16);
    cudaGetSymbolAddress((void**)&yh,  g_yh);
    cudaGetSymbolAddress((void**)&yl,  g_yl);

    cudaFuncSetAttribute(encoder_layer_tc<true >,
                         cudaFuncAttributeMaxDynamicSharedMemorySize, SMEM_BYTES);
    cudaFuncSetAttribute(encoder_layer_tc<false>,
                         cudaFuncAttributeMaxDynamicSharedMemorySize, SMEM_BYTES);

    const int total4 = B * L * D / 4;               // exactly divisible
    convert_split<<<total4 / 256, 256>>>(samples, x16, xh, xl);

    dim3 grid(NT, B * H);                           // 16 x 128
    encoder_layer_tc<true ><<<grid, 128, SMEM_BYTES>>>(x16, xh, xl, weights,
                                                       y16, yh, yl, nullptr);
    encoder_layer_tc<false><<<grid, 128, SMEM_BYTES>>>(y16, yh, yl, weights + H * 6,
                                                       nullptr, nullptr, nullptr, out);
}

// round 16
// speedup vs baseline: 1.4885x; 1.2631x over previous
#include <cuda_runtime.h>
#include <cuda_bf16.h>
#include <cuda_fp16.h>
#include <cmath>
#include <cstdint>

// Problem constants (fixed by setup_inputs: B=8, L=20*50+1, d_model=1024, H=16, 2 layers)
namespace {
constexpr int B    = 8;
constexpr int L    = 1001;
constexpr int D    = 1024;
constexpr int H    = 16;
constexpr int DK   = 64;
constexpr int NKQ  = 1000;   // query row index
constexpr int KCLS = 50;     // class block size
constexpr int TI   = 64;     // row tile (4 warps x 16)
constexpr int TJ   = 64;     // key tile
constexpr int NT   = (L + TJ - 1) / TJ;   // 16
constexpr int LDS  = 72;     // elems per smem row (144B stride: conflict-free ldmatrix)
constexpr int TILE = TJ * LDS;            // elems per tile plane
constexpr int KB2  = 2 * TILE;            // K buffer: [f16 hi | f16 lo]
constexpr int SMEM_BYTES = (2 * KB2 + TILE) * 2;  // 2 K bufs + 1 fp16 Q = 46080 B
// Per-row re-centered softmax: exponent_e = (s - s_diag)/8 - 2, i.e.
// e = 2^(s*C1 + c0_row), c0_row = -nd*C1 + EXPB. Diag P == e^-2 = 0.135; all
// significant P values are fp16-normal for every head/layer. The row-common
// scale cancels exactly in o/l.
constexpr float C1   = 0.125f * 1.4426950408889634f;
constexpr float EXPB = -2.0f * 1.4426950408889634f;
}

// activations as fp16 hi/lo pairs (x = x16 + xlo exact to 2^-22; global scratch).
__device__ __half g_x16[(size_t)B * L * D];
__device__ __half g_xlo[(size_t)B * L * D];
__device__ __half g_y16[(size_t)B * L * D];
__device__ __half g_ylo[(size_t)B * L * D];

__device__ __forceinline__ uint32_t smem_u32(const void* p) {
    return (uint32_t)__cvta_generic_to_shared(p);
}
__device__ __forceinline__ void ldmx4(uint32_t a, uint32_t& r0, uint32_t& r1, uint32_t& r2, uint32_t& r3) {
    asm volatile("ldmatrix.sync.aligned.m8n8.x4.shared.b16 {%0,%1,%2,%3},[%4];"
                 : "=r"(r0), "=r"(r1), "=r"(r2), "=r"(r3) : "r"(a));
}
__device__ __forceinline__ void ldmx4t(uint32_t a, uint32_t& r0, uint32_t& r1, uint32_t& r2, uint32_t& r3) {
    asm volatile("ldmatrix.sync.aligned.m8n8.x4.trans.shared.b16 {%0,%1,%2,%3},[%4];"
                 : "=r"(r0), "=r"(r1), "=r"(r2), "=r"(r3) : "r"(a));
}
__device__ __forceinline__ void mma_f16(float* d, const uint32_t* a, uint32_t b0, uint32_t b1) {
    asm volatile("mma.sync.aligned.m16n8k16.row.col.f32.f16.f16.f32 "
                 "{%0,%1,%2,%3},{%4,%5,%6,%7},{%8,%9},{%0,%1,%2,%3};"
                 : "+f"(d[0]), "+f"(d[1]), "+f"(d[2]), "+f"(d[3])
                 : "r"(a[0]), "r"(a[1]), "r"(a[2]), "r"(a[3]), "r"(b0), "r"(b1));
}
__device__ __forceinline__ float ex2(float x) {
    float r; asm("ex2.approx.ftz.f32 %0,%1;" : "=f"(r) : "f"(x)); return r;
}
__device__ __forceinline__ uint32_t pack_h2(float a, float b) {
    __half2 h = __floats2half2_rn(a, b);
    return *reinterpret_cast<uint32_t*>(&h);
}
// fp16 hi/lo split of pair (a,b): a -> low halves, b -> high halves.
__device__ __forceinline__ void split2h(float a, float b, uint32_t& hi, uint32_t& lo) {
    __half2 h = __floats2half2_rn(a, b);
    float2 hf = __half22float2(h);
    __half2 l = __floats2half2_rn(a - hf.x, b - hf.y);
    hi = *reinterpret_cast<uint32_t*>(&h);
    lo = *reinterpret_cast<uint32_t*>(&l);
}
__device__ __forceinline__ void cp_commit() { asm volatile("cp.async.commit_group;"); }
template<int N> __device__ __forceinline__ void cp_wait() {
    asm volatile("cp.async.wait_group %0;" :: "n"(N));
}

// Async-stage a K tile: [f16 hi | f16 lo] planes (64 rows x this head's 64 cols).
__device__ __forceinline__ void stage_k(const __half* __restrict__ g16,
                                        const __half* __restrict__ glo,
                                        int base_row, __half* sbuf, int tid) {
#pragma unroll
    for (int it = 0; it < 8; ++it) {
        int idx = tid + 128 * it;          // 0..1023
        int arr = idx >> 9;                // 0 = f16 hi, 1 = f16 lo
        int rem = idx & 511;
        int row = rem >> 3;
        int ch  = rem & 7;                 // 16B chunk within 128B row segment
        int g   = base_row + row;
        const void* src = (arr ? glo : g16) + (size_t)g * D + ch * 8;
        uint32_t dst = smem_u32(sbuf + arr * TILE + row * LDS + ch * 8);
        int sz = (g < L) ? 16 : 0;
        asm volatile("cp.async.ca.shared.global [%0], [%1], 16, %2;"
                     :: "r"(dst), "l"(src), "r"(sz));
    }
}
// Async-stage the fp16 Q tile (512 chunks / 128 threads = 4 per thread).
__device__ __forceinline__ void stage_q(const __half* __restrict__ g16,
                                        int base_row, __half* qb, int tid) {
#pragma unroll
    for (int it = 0; it < 4; ++it) {
        int idx = tid + 128 * it;          // 0..511
        int row = idx >> 3;
        int ch  = idx & 7;
        int g   = base_row + row;
        const void* src = g16 + (size_t)g * D + ch * 8;
        uint32_t dst = smem_u32(qb + row * LDS + ch * 8);
        int sz = (g < L) ? 16 : 0;
        asm volatile("cp.async.ca.shared.global [%0], [%1], 16, %2;"
                     :: "r"(dst), "l"(src), "r"(sz));
    }
}

// ---- S = fl16(Q) fl16(K)^T : single-term fp16 GEMM (32 MMAs/warp-tile) ----
__device__ __forceinline__ void s_phase(const __half* kb, const uint32_t (&qf)[4][4],
                                        float (&acc)[8][4], int lrK, int lcK) {
#pragma unroll
    for (int nt = 0; nt < 8; ++nt)
#pragma unroll
        for (int v = 0; v < 4; ++v) acc[nt][v] = 0.f;
#pragma unroll
    for (int kc = 0; kc < 4; ++kc) {
#pragma unroll
        for (int ntp = 0; ntp < 4; ++ntp) {
            const int off = (16 * ntp + lrK) * LDS + kc * 16 + lcK;
            uint32_t b0, b1, b2, b3;
            ldmx4(smem_u32(kb + off), b0, b1, b2, b3);
            mma_f16(acc[2 * ntp],     qf[kc], b0, b1);
            mma_f16(acc[2 * ntp + 1], qf[kc], b2, b3);
        }
    }
}

// ---- O += P V : fp16 P (single term) x fp16 hi/lo V (2 terms, 64 MMAs) ----
__device__ __forceinline__ void pv_phase(const __half* kb,
                                         const uint32_t (&ap)[4][4],
                                         float (&o)[8][4], int lrA, int lcA) {
    const __half* vh = kb;             // f16 hi plane (same data S used)
    const __half* vl = kb + TILE;      // f16 lo plane
#pragma unroll
    for (int kc = 0; kc < 4; ++kc) {
#pragma unroll
        for (int ntp = 0; ntp < 4; ++ntp) {
            const int off = (kc * 16 + lrA) * LDS + 16 * ntp + lcA;
            uint32_t vh0, vh1, vh2, vh3, vl0, vl1, vl2, vl3;
            ldmx4t(smem_u32(vh + off), vh0, vh1, vh2, vh3);
            ldmx4t(smem_u32(vl + off), vl0, vl1, vl2, vl3);
            mma_f16(o[2 * ntp],     ap[kc], vh0, vh1);
            mma_f16(o[2 * ntp],     ap[kc], vl0, vl1);
            mma_f16(o[2 * ntp + 1], ap[kc], vh2, vh3);
            mma_f16(o[2 * ntp + 1], ap[kc], vl2, vl3);
        }
    }
}

// Softmax + structured multiplier + pack P into fp16 A-fragments.
// Per-row centering via c00/c01. DIAG: override the MMA score with the exact
// fp32 self-dot AND record the fp16 rounding residual of the diag P (dp0/dp1)
// for the exact-correction pass after pv_phase.
template<bool MASK, bool DIAG>
__device__ __forceinline__ void softmax_pack(const float (&acc)[8][4], int j_base,
                                             int gi0, int gi1, int jlo0, int jlo1,
                                             float nd0, float nd1, float c00, float c01,
                                             const float* wr0, const float* wr1,
                                             uint32_t (&ap)[4][4],
                                             float& l0, float& l1,
                                             float& dp0, float& dp1, int lane)
{
#pragma unroll
    for (int nt = 0; nt < 8; ++nt) {
        const int gj0 = j_base + nt * 8 + (lane & 3) * 2;
        const int gj1 = gj0 + 1;
        float a00 = acc[nt][0], a01 = acc[nt][1], a10 = acc[nt][2], a11 = acc[nt][3];
        if (DIAG) {
            if (gj0 == gi0) a00 = nd0;
            if (gj1 == gi0) a01 = nd0;
            if (gj0 == gi1) a10 = nd1;
            if (gj1 == gi1) a11 = nd1;
        }
        float e00 = ex2(fmaf(a00, C1, c00));
        float e01 = ex2(fmaf(a01, C1, c00));
        float e10 = ex2(fmaf(a10, C1, c01));
        float e11 = ex2(fmaf(a11, C1, c01));
        if (MASK) {
            if (gj0 >= L) { e00 = 0.f; e10 = 0.f; }
            if (gj1 >= L) { e01 = 0.f; e11 = 0.f; }
        }
        l0 += e00 + e01;
        l1 += e10 + e11;
        float t00 = ((unsigned)(gj0 - jlo0) < (unsigned)KCLS) ? wr0[0] : wr0[1];
        float t01 = ((unsigned)(gj1 - jlo0) < (unsigned)KCLS) ? wr0[0] : wr0[1];
        float t10 = ((unsigned)(gj0 - jlo1) < (unsigned)KCLS) ? wr1[0] : wr1[1];
        float t11 = ((unsigned)(gj1 - jlo1) < (unsigned)KCLS) ? wr1[0] : wr1[1];
        if (gj0 == gi0) t00 = wr0[2];
        if (gj1 == gi0) t01 = wr0[2];
        if (gj0 == gi1) t10 = wr1[2];
        if (gj1 == gi1) t11 = wr1[2];
        if (gj0 == NKQ) { t00 = wr0[3]; t10 = wr1[3]; }
        if (gj1 == NKQ) { t01 = wr0[3]; t11 = wr1[3]; }
        const float p00 = e00 * t00, p01 = e01 * t01;
        const float p10 = e10 * t10, p11 = e11 * t11;
        if (DIAG) {   // residual of the diag P under fp16 rounding
            if (gj0 == gi0) dp0 = p00 - __half2float(__float2half_rn(p00));
            if (gj1 == gi0) dp0 = p01 - __half2float(__float2half_rn(p01));
            if (gj0 == gi1) dp1 = p10 - __half2float(__float2half_rn(p10));
            if (gj1 == gi1) dp1 = p11 - __half2float(__float2half_rn(p11));
        }
        const int kc = nt >> 1, of = (nt & 1) * 2;
        ap[kc][of]     = pack_h2(p00, p01);
        ap[kc][of + 1] = pack_h2(p10, p11);
    }
}

// exact fp32 row self-dot: 16 cols starting at part*16 of (x16+xlo)
__device__ __forceinline__ float ndot_part(const __half* rh, const __half* rl, int part) {
    const uint4* ph = reinterpret_cast<const uint4*>(rh + part * 16);
    const uint4* pl = reinterpret_cast<const uint4*>(rl + part * 16);
    float s = 0.f;
#pragma unroll
    for (int q = 0; q < 2; ++q) {
        uint4 hw = ph[q], lw = pl[q];
        const uint32_t hv[4] = {hw.x, hw.y, hw.z, hw.w};
        const uint32_t lv[4] = {lw.x, lw.y, lw.z, lw.w};
#pragma unroll
        for (int i = 0; i < 4; ++i) {
            float2 h2 = __half22float2(*reinterpret_cast<const __half2*>(&hv[i]));
            float2 l2 = __half22float2(*reinterpret_cast<const __half2*>(&lv[i]));
            float v0 = h2.x + l2.x;
            float v1 = h2.y + l2.y;
            s = fmaf(v0, v0, s);
            s = fmaf(v1, v1, s);
        }
    }
    return s;
}

// Initial fp32 -> fp16 hi/lo (one-time).
__global__ void convert_split(const float* __restrict__ x,
                              __half* __restrict__ x16,
                              __half* __restrict__ xlo) {
    size_t i = ((size_t)blockIdx.x * blockDim.x + threadIdx.x) * 4;
    float4 v = *reinterpret_cast<const float4*>(x + i);
    uint32_t h0, l0, h1, l1;
    split2h(v.x, v.y, h0, l0);
    split2h(v.z, v.w, h1, l1);
    *reinterpret_cast<uint2*>(x16 + i) = make_uint2(h0, h1);
    *reinterpret_cast<uint2*>(xlo + i) = make_uint2(l0, l1);
}

template<bool SPLIT_OUT>
__global__ void __launch_bounds__(128, 3)
encoder_layer_tc(const __half* __restrict__ x16,
                 const __half* __restrict__ xlo,
                 const float* __restrict__ w6,        // [H][6] for this layer
                 __half* __restrict__ y16,            // SPLIT_OUT
                 __half* __restrict__ ylo,            // SPLIT_OUT
                 float* __restrict__ yo)              // !SPLIT_OUT
{
    extern __shared__ __half sbuf[];            // [K0(2T)][K1(2T)][Q(1T)]

    const int tid  = threadIdx.x;
    const int w    = tid >> 5;
    const int lane = tid & 31;
    const int h    = blockIdx.y & (H - 1);
    const int b    = blockIdx.y >> 4;
    const int i_base = blockIdx.x * TI;

    const size_t slice = (size_t)b * L * D + h * DK;
    const __half* x16b = x16 + slice;
    const __half* xlob = xlo + slice;
    __half* qb = sbuf + 2 * KB2;                // resident fp16 Q buffer

    float t6[6];
#pragma unroll
    for (int q = 0; q < 6; ++q) t6[q] = tanhf(w6[h * 6 + q]);

    // lane-derived ldmatrix offset pieces
    const int lrA = (lane & 7) + ((lane >> 3) & 1) * 8;  // A / trans-B row part
    const int lcA = ((lane >> 4) & 1) * 8;               // A / trans-B col part
    const int lrK = (lane & 7) + ((lane >> 4) & 1) * 8;  // non-trans B row part
    const int lcK = ((lane >> 3) & 1) * 8;               // non-trans B col part

    // prologue: Q -> qb, K0 -> buf0, K1 -> buf1 (separate groups)
    stage_q(x16b, i_base, qb, tid);                 cp_commit();
    stage_k(x16b, xlob, 0,  sbuf,       tid);       cp_commit();
    stage_k(x16b, xlob, TJ, sbuf + KB2, tid);       cp_commit();

    const int gi0 = i_base + w * 16 + (lane >> 2);
    const int gi1 = gi0 + 8;
    const int jlo0 = (gi0 / KCLS) * KCLS;
    const int jlo1 = (gi1 / KCLS) * KCLS;
    float wr0[4], wr1[4];
    if (gi0 == NKQ) { wr0[0] = wr0[1] = t6[4]; wr0[2] = wr0[3] = t6[5]; }
    else            { wr0[0] = t6[1]; wr0[1] = t6[2]; wr0[2] = t6[0]; wr0[3] = t6[3]; }
    if (gi1 == NKQ) { wr1[0] = wr1[1] = t6[4]; wr1[2] = wr1[3] = t6[5]; }
    else            { wr1[0] = t6[1]; wr1[1] = t6[2]; wr1[2] = t6[0]; wr1[3] = t6[3]; }

    // exact diag scores (fp32 self-dot of x16+xlo); quad lanes split 16 cols each
    float nd0 = 0.f, nd1 = 0.f;
    {
        const int part = lane & 3;
        if (gi0 < L) nd0 = ndot_part(x16b + (size_t)gi0 * D, xlob + (size_t)gi0 * D, part);
        if (gi1 < L) nd1 = ndot_part(x16b + (size_t)gi1 * D, xlob + (size_t)gi1 * D, part);
        nd0 += __shfl_xor_sync(0xffffffffu, nd0, 1);
        nd0 += __shfl_xor_sync(0xffffffffu, nd0, 2);
        nd1 += __shfl_xor_sync(0xffffffffu, nd1, 1);
        nd1 += __shfl_xor_sync(0xffffffffu, nd1, 2);
    }
    // per-row fixed base: exponent_e = (s - nd)/8 - 2  (diag P == e^-2, fp16-normal)
    const float c00 = fmaf(-nd0, C1, EXPB);
    const float c01 = fmaf(-nd1, C1, EXPB);

    cp_wait<2>();            // Q landed
    __syncthreads();

    // hoist fp16 Q A-fragments (16 regs)
    uint32_t qf[4][4];
#pragma unroll
    for (int kc = 0; kc < 4; ++kc) {
        const int off = (w * 16 + lrA) * LDS + kc * 16 + lcA;
        ldmx4(smem_u32(qb + off), qf[kc][0], qf[kc][1], qf[kc][2], qf[kc][3]);
    }

    float o[8][4];
#pragma unroll
    for (int nt = 0; nt < 8; ++nt)
#pragma unroll
        for (int v = 0; v < 4; ++v) o[nt][v] = 0.f;
    float l0 = 0.f, l1 = 0.f;

    const int diag_jt = blockIdx.x;     // TI == TJ: the diagonal falls in this j-tile

    for (int jt = 0; jt < NT; ++jt) {
        const __half* kb = sbuf + (jt & 1) * KB2;   // K(jt)

        cp_wait<1>();        // K(jt) landed; K(jt+1) may be in flight
        __syncthreads();

        float acc[8][4];
        s_phase(kb, qf, acc, lrK, lcK);

        uint32_t ap[4][4];
        float dp0 = 0.f, dp1 = 0.f;
        if (jt == NT - 1) {
            if (jt == diag_jt)
                softmax_pack<true , true >(acc, jt * TJ, gi0, gi1, jlo0, jlo1, nd0, nd1,
                                           c00, c01, wr0, wr1, ap, l0, l1, dp0, dp1, lane);
            else
                softmax_pack<true , false>(acc, jt * TJ, gi0, gi1, jlo0, jlo1, nd0, nd1,
                                           c00, c01, wr0, wr1, ap, l0, l1, dp0, dp1, lane);
        } else {
            if (jt == diag_jt)
                softmax_pack<false, true >(acc, jt * TJ, gi0, gi1, jlo0, jlo1, nd0, nd1,
                                           c00, c01, wr0, wr1, ap, l0, l1, dp0, dp1, lane);
            else
                softmax_pack<false, false>(acc, jt * TJ, gi0, gi1, jlo0, jlo1, nd0, nd1,
                                           c00, c01, wr0, wr1, ap, l0, l1, dp0, dp1, lane);
        }

        pv_phase(kb, ap, o, lrA, lcA);

        // exact diag-P correction: o += (P_fp32 - fp16(P)) * v over the full row.
        // The diag element is owned by one lane of each row-quad; share it.
        if (jt == diag_jt) {
            dp0 += __shfl_xor_sync(0xffffffffu, dp0, 1);
            dp0 += __shfl_xor_sync(0xffffffffu, dp0, 2);
            dp1 += __shfl_xor_sync(0xffffffffu, dp1, 1);
            dp1 += __shfl_xor_sync(0xffffffffu, dp1, 2);
            const int lr0 = w * 16 + (lane >> 2);   // local row of gi0 in this tile
            const int lr1 = lr0 + 8;
#pragma unroll
            for (int nt = 0; nt < 8; ++nt) {
                const int c = nt * 8 + (lane & 3) * 2;
                float2 vh0 = __half22float2(*reinterpret_cast<const __half2*>(kb + lr0 * LDS + c));
                float2 vl0 = __half22float2(*reinterpret_cast<const __half2*>(kb + TILE + lr0 * LDS + c));
                o[nt][0] = fmaf(dp0, vh0.x + vl0.x, o[nt][0]);
                o[nt][1] = fmaf(dp0, vh0.y + vl0.y, o[nt][1]);
                float2 vh1 = __half22float2(*reinterpret_cast<const __half2*>(kb + lr1 * LDS + c));
                float2 vl1 = __half22float2(*reinterpret_cast<const __half2*>(kb + TILE + lr1 * LDS + c));
                o[nt][2] = fmaf(dp1, vh1.x + vl1.x, o[nt][2]);
                o[nt][3] = fmaf(dp1, vh1.y + vl1.y, o[nt][3]);
            }
        }

        __syncthreads();     // all warps done reading kb before restaging it
        if (jt + 2 < NT)
            stage_k(x16b, xlob, (jt + 2) * TJ, sbuf + (jt & 1) * KB2, tid);
        cp_commit();         // always commit (possibly empty) to keep wait bookkeeping exact
    }

    // ---- epilogue: reduce denominators once, divide, write ----
    l0 += __shfl_xor_sync(0xffffffffu, l0, 1);
    l0 += __shfl_xor_sync(0xffffffffu, l0, 2);
    l1 += __shfl_xor_sync(0xffffffffu, l1, 1);
    l1 += __shfl_xor_sync(0xffffffffu, l1, 2);
    const float inv0 = 1.f / l0, inv1 = 1.f / l1;

#pragma unroll
    for (int nt = 0; nt < 8; ++nt) {
        const int c = nt * 8 + (lane & 3) * 2;
        if (SPLIT_OUT) {
            if (gi0 < L) {
                uint32_t hi, lo;
                split2h(o[nt][0] * inv0, o[nt][1] * inv0, hi, lo);
                *reinterpret_cast<uint32_t*>(y16 + slice + (size_t)gi0 * D + c) = hi;
                *reinterpret_cast<uint32_t*>(ylo + slice + (size_t)gi0 * D + c) = lo;
            }
            if (gi1 < L) {
                uint32_t hi, lo;
                split2h(o[nt][2] * inv1, o[nt][3] * inv1, hi, lo);
                *reinterpret_cast<uint32_t*>(y16 + slice + (size_t)gi1 * D + c) = hi;
                *reinterpret_cast<uint32_t*>(ylo + slice + (size_t)gi1 * D + c) = lo;
            }
        } else {
            if (gi0 < L)
                *reinterpret_cast<float2*>(yo + slice + (size_t)gi0 * D + c) =
                    make_float2(o[nt][0] * inv0, o[nt][1] * inv0);
            if (gi1 < L)
                *reinterpret_cast<float2*>(yo + slice + (size_t)gi1 * D + c) =
                    make_float2(o[nt][2] * inv1, o[nt][3] * inv1);
        }
    }
}

extern "C" void kernel_launch(void* const* d_in, const int* in_sizes, int n_in,
                              void* d_out, int out_size)
{
    const float* samples = (const float*)d_in[0];   // [B, L, D] fp32
    const float* weights = (const float*)d_in[1];   // [2, H, 6] fp32
    float* out = (float*)d_out;                     // [B, L, D] fp32

    __half *x16, *xlo, *y16, *ylo;
    cudaGetSymbolAddress((void**)&x16, g_x16);
    cudaGetSymbolAddress((void**)&xlo, g_xlo);
    cudaGetSymbolAddress((void**)&y16, g_y16);
    cudaGetSymbolAddress((void**)&ylo, g_ylo);

    cudaFuncSetAttribute(encoder_layer_tc<true >,
                         cudaFuncAttributeMaxDynamicSharedMemorySize, SMEM_BYTES);
    cudaFuncSetAttribute(encoder_layer_tc<false>,
                         cudaFuncAttributeMaxDynamicSharedMemorySize, SMEM_BYTES);

    const int total4 = B * L * D / 4;               // exactly divisible
    convert_split<<<total4 / 256, 256>>>(samples, x16, xlo);

    dim3 grid(NT, B * H);                           // 16 x 128
    encoder_layer_tc<true ><<<grid, 128, SMEM_BYTES>>>(x16, xlo, weights, y16, ylo, nullptr);
    encoder_layer_tc<false><<<grid, 128, SMEM_BYTES>>>(y16, ylo, weights + H * 6,
                                                       nullptr, nullptr, out);
}

// round 17
// speedup vs baseline: 1.9105x; 1.2835x over previous
#include <cuda_runtime.h>
#include <cuda_bf16.h>
#include <cuda_fp16.h>
#include <cmath>
#include <cstdint>

// Problem constants (fixed by setup_inputs: B=8, L=20*50+1, d_model=1024, H=16, 2 layers)
namespace {
constexpr int B    = 8;
constexpr int L    = 1001;
constexpr int D    = 1024;
constexpr int H    = 16;
constexpr int DK   = 64;
constexpr int NKQ  = 1000;   // query row index
constexpr int KCLS = 50;     // class block size
constexpr int TI   = 64;     // row tile (4 warps x 16)
constexpr int TJ   = 64;     // key tile
constexpr int NT   = (L + TJ - 1) / TJ;   // 16
constexpr int LDS  = 72;     // elems per smem row (144B stride: conflict-free ldmatrix)
constexpr int TILE = TJ * LDS;            // elems per tile plane
constexpr int SMEM_BYTES = 3 * TILE * 2;  // 2 K bufs (hi only) + 1 fp16 Q = 27648 B
// Per-row re-centered softmax: exponent_e = (s - s_diag)/8 - 2, i.e.
// e = 2^(s*C1 + c0_row), c0_row = -nd*C1 + EXPB. Diag P == e^-2 = 0.135; all
// significant P values are fp16-normal for every head/layer. The row-common
// scale cancels exactly in o/l.
constexpr float C1   = 0.125f * 1.4426950408889634f;
constexpr float EXPB = -2.0f * 1.4426950408889634f;
}

// activations as fp16 hi/lo pairs (x = x16 + xlo exact to 2^-22; global scratch).
__device__ __half g_x16[(size_t)B * L * D];
__device__ __half g_xlo[(size_t)B * L * D];
__device__ __half g_y16[(size_t)B * L * D];
__device__ __half g_ylo[(size_t)B * L * D];

__device__ __forceinline__ uint32_t smem_u32(const void* p) {
    return (uint32_t)__cvta_generic_to_shared(p);
}
__device__ __forceinline__ void ldmx4(uint32_t a, uint32_t& r0, uint32_t& r1, uint32_t& r2, uint32_t& r3) {
    asm volatile("ldmatrix.sync.aligned.m8n8.x4.shared.b16 {%0,%1,%2,%3},[%4];"
                 : "=r"(r0), "=r"(r1), "=r"(r2), "=r"(r3) : "r"(a));
}
__device__ __forceinline__ void ldmx4t(uint32_t a, uint32_t& r0, uint32_t& r1, uint32_t& r2, uint32_t& r3) {
    asm volatile("ldmatrix.sync.aligned.m8n8.x4.trans.shared.b16 {%0,%1,%2,%3},[%4];"
                 : "=r"(r0), "=r"(r1), "=r"(r2), "=r"(r3) : "r"(a));
}
__device__ __forceinline__ void mma_f16(float* d, const uint32_t* a, uint32_t b0, uint32_t b1) {
    asm volatile("mma.sync.aligned.m16n8k16.row.col.f32.f16.f16.f32 "
                 "{%0,%1,%2,%3},{%4,%5,%6,%7},{%8,%9},{%0,%1,%2,%3};"
                 : "+f"(d[0]), "+f"(d[1]), "+f"(d[2]), "+f"(d[3])
                 : "r"(a[0]), "r"(a[1]), "r"(a[2]), "r"(a[3]), "r"(b0), "r"(b1));
}
__device__ __forceinline__ float ex2(float x) {
    float r; asm("ex2.approx.ftz.f32 %0,%1;" : "=f"(r) : "f"(x)); return r;
}
__device__ __forceinline__ uint32_t pack_h2(float a, float b) {
    __half2 h = __floats2half2_rn(a, b);
    return *reinterpret_cast<uint32_t*>(&h);
}
// fp16 hi/lo split of pair (a,b): a -> low halves, b -> high halves.
__device__ __forceinline__ void split2h(float a, float b, uint32_t& hi, uint32_t& lo) {
    __half2 h = __floats2half2_rn(a, b);
    float2 hf = __half22float2(h);
    __half2 l = __floats2half2_rn(a - hf.x, b - hf.y);
    hi = *reinterpret_cast<uint32_t*>(&h);
    lo = *reinterpret_cast<uint32_t*>(&l);
}
__device__ __forceinline__ void cp_commit() { asm volatile("cp.async.commit_group;"); }
template<int N> __device__ __forceinline__ void cp_wait() {
    asm volatile("cp.async.wait_group %0;" :: "n"(N));
}

// Async-stage a K tile (fp16 hi plane only: 64 rows x this head's 64 cols).
// 512 16B chunks / 128 threads = 4 per thread. OOB rows zero-filled via src-size=0.
__device__ __forceinline__ void stage_k(const __half* __restrict__ g16,
                                        int base_row, __half* sbuf, int tid) {
#pragma unroll
    for (int it = 0; it < 4; ++it) {
        int idx = tid + 128 * it;          // 0..511
        int row = idx >> 3;
        int ch  = idx & 7;                 // 16B chunk within 128B row segment
        int g   = base_row + row;
        const void* src = g16 + (size_t)g * D + ch * 8;
        uint32_t dst = smem_u32(sbuf + row * LDS + ch * 8);
        int sz = (g < L) ? 16 : 0;
        asm volatile("cp.async.ca.shared.global [%0], [%1], 16, %2;"
                     :: "r"(dst), "l"(src), "r"(sz));
    }
}

// ---- S = fl16(Q) fl16(K)^T : single-term fp16 GEMM (32 MMAs/warp-tile) ----
__device__ __forceinline__ void s_phase(const __half* kb, const uint32_t (&qf)[4][4],
                                        float (&acc)[8][4], int lrK, int lcK) {
#pragma unroll
    for (int nt = 0; nt < 8; ++nt)
#pragma unroll
        for (int v = 0; v < 4; ++v) acc[nt][v] = 0.f;
#pragma unroll
    for (int kc = 0; kc < 4; ++kc) {
#pragma unroll
        for (int ntp = 0; ntp < 4; ++ntp) {
            const int off = (16 * ntp + lrK) * LDS + kc * 16 + lcK;
            uint32_t b0, b1, b2, b3;
            ldmx4(smem_u32(kb + off), b0, b1, b2, b3);
            mma_f16(acc[2 * ntp],     qf[kc], b0, b1);
            mma_f16(acc[2 * ntp + 1], qf[kc], b2, b3);
        }
    }
}

// ---- O += P V : fp16 P x fp16 V-hi (32 MMAs; V-lo handled by diag repair) ----
__device__ __forceinline__ void pv_phase(const __half* kb,
                                         const uint32_t (&ap)[4][4],
                                         float (&o)[8][4], int lrA, int lcA) {
#pragma unroll
    for (int kc = 0; kc < 4; ++kc) {
#pragma unroll
        for (int ntp = 0; ntp < 4; ++ntp) {
            const int off = (kc * 16 + lrA) * LDS + 16 * ntp + lcA;
            uint32_t v0, v1, v2, v3;
            ldmx4t(smem_u32(kb + off), v0, v1, v2, v3);
            mma_f16(o[2 * ntp],     ap[kc], v0, v1);
            mma_f16(o[2 * ntp + 1], ap[kc], v2, v3);
        }
    }
}

// Softmax + structured multiplier + pack P into fp16 A-fragments.
// Per-row centering via c00/c01. DIAG: override the MMA score with the exact
// fp32 self-dot AND record the full diag P (pf*) + its fp16 rounding residual
// (dp*) for the exact-correction pass after pv_phase.
template<bool MASK, bool DIAG>
__device__ __forceinline__ void softmax_pack(const float (&acc)[8][4], int j_base,
                                             int gi0, int gi1, int jlo0, int jlo1,
                                             float nd0, float nd1, float c00, float c01,
                                             const float* wr0, const float* wr1,
                                             uint32_t (&ap)[4][4],
                                             float& l0, float& l1,
                                             float& dp0, float& dp1,
                                             float& pf0, float& pf1, int lane)
{
#pragma unroll
    for (int nt = 0; nt < 8; ++nt) {
        const int gj0 = j_base + nt * 8 + (lane & 3) * 2;
        const int gj1 = gj0 + 1;
        float a00 = acc[nt][0], a01 = acc[nt][1], a10 = acc[nt][2], a11 = acc[nt][3];
        if (DIAG) {
            if (gj0 == gi0) a00 = nd0;
            if (gj1 == gi0) a01 = nd0;
            if (gj0 == gi1) a10 = nd1;
            if (gj1 == gi1) a11 = nd1;
        }
        float e00 = ex2(fmaf(a00, C1, c00));
        float e01 = ex2(fmaf(a01, C1, c00));
        float e10 = ex2(fmaf(a10, C1, c01));
        float e11 = ex2(fmaf(a11, C1, c01));
        if (MASK) {
            if (gj0 >= L) { e00 = 0.f; e10 = 0.f; }
            if (gj1 >= L) { e01 = 0.f; e11 = 0.f; }
        }
        l0 += e00 + e01;
        l1 += e10 + e11;
        float t00 = ((unsigned)(gj0 - jlo0) < (unsigned)KCLS) ? wr0[0] : wr0[1];
        float t01 = ((unsigned)(gj1 - jlo0) < (unsigned)KCLS) ? wr0[0] : wr0[1];
        float t10 = ((unsigned)(gj0 - jlo1) < (unsigned)KCLS) ? wr1[0] : wr1[1];
        float t11 = ((unsigned)(gj1 - jlo1) < (unsigned)KCLS) ? wr1[0] : wr1[1];
        if (gj0 == gi0) t00 = wr0[2];
        if (gj1 == gi0) t01 = wr0[2];
        if (gj0 == gi1) t10 = wr1[2];
        if (gj1 == gi1) t11 = wr1[2];
        if (gj0 == NKQ) { t00 = wr0[3]; t10 = wr1[3]; }
        if (gj1 == NKQ) { t01 = wr0[3]; t11 = wr1[3]; }
        const float p00 = e00 * t00, p01 = e01 * t01;
        const float p10 = e10 * t10, p11 = e11 * t11;
        if (DIAG) {   // full diag P + its fp16 rounding residual
            if (gj0 == gi0) { pf0 = p00; dp0 = p00 - __half2float(__float2half_rn(p00)); }
            if (gj1 == gi0) { pf0 = p01; dp0 = p01 - __half2float(__float2half_rn(p01)); }
            if (gj0 == gi1) { pf1 = p10; dp1 = p10 - __half2float(__float2half_rn(p10)); }
            if (gj1 == gi1) { pf1 = p11; dp1 = p11 - __half2float(__float2half_rn(p11)); }
        }
        const int kc = nt >> 1, of = (nt & 1) * 2;
        ap[kc][of]     = pack_h2(p00, p01);
        ap[kc][of + 1] = pack_h2(p10, p11);
    }
}

// exact fp32 row self-dot: 16 cols starting at part*16 of (x16+xlo)
__device__ __forceinline__ float ndot_part(const __half* rh, const __half* rl, int part) {
    const uint4* ph = reinterpret_cast<const uint4*>(rh + part * 16);
    const uint4* pl = reinterpret_cast<const uint4*>(rl + part * 16);
    float s = 0.f;
#pragma unroll
    for (int q = 0; q < 2; ++q) {
        uint4 hw = ph[q], lw = pl[q];
        const uint32_t hv[4] = {hw.x, hw.y, hw.z, hw.w};
        const uint32_t lv[4] = {lw.x, lw.y, lw.z, lw.w};
#pragma unroll
        for (int i = 0; i < 4; ++i) {
            float2 h2 = __half22float2(*reinterpret_cast<const __half2*>(&hv[i]));
            float2 l2 = __half22float2(*reinterpret_cast<const __half2*>(&lv[i]));
            float v0 = h2.x + l2.x;
            float v1 = h2.y + l2.y;
            s = fmaf(v0, v0, s);
            s = fmaf(v1, v1, s);
        }
    }
    return s;
}

// Initial fp32 -> fp16 hi/lo (one-time).
__global__ void convert_split(const float* __restrict__ x,
                              __half* __restrict__ x16,
                              __half* __restrict__ xlo) {
    size_t i = ((size_t)blockIdx.x * blockDim.x + threadIdx.x) * 4;
    float4 v = *reinterpret_cast<const float4*>(x + i);
    uint32_t h0, l0, h1, l1;
    split2h(v.x, v.y, h0, l0);
    split2h(v.z, v.w, h1, l1);
    *reinterpret_cast<uint2*>(x16 + i) = make_uint2(h0, h1);
    *reinterpret_cast<uint2*>(xlo + i) = make_uint2(l0, l1);
}

template<bool SPLIT_OUT>
__global__ void __launch_bounds__(128, 3)
encoder_layer_tc(const __half* __restrict__ x16,
                 const __half* __restrict__ xlo,
                 const float* __restrict__ w6,        // [H][6] for this layer
                 __half* __restrict__ y16,            // SPLIT_OUT
                 __half* __restrict__ ylo,            // SPLIT_OUT
                 float* __restrict__ yo)              // !SPLIT_OUT
{
    extern __shared__ __half sbuf[];            // [K0(1T)][K1(1T)][Q(1T)]

    const int tid  = threadIdx.x;
    const int w    = tid >> 5;
    const int lane = tid & 31;
    const int h    = blockIdx.y & (H - 1);
    const int b    = blockIdx.y >> 4;
    const int i_base = blockIdx.x * TI;

    const size_t slice = (size_t)b * L * D + h * DK;
    const __half* x16b = x16 + slice;
    const __half* xlob = xlo + slice;
    __half* qb = sbuf + 2 * TILE;               // resident fp16 Q buffer

    float t6[6];
#pragma unroll
    for (int q = 0; q < 6; ++q) t6[q] = tanhf(w6[h * 6 + q]);

    // lane-derived ldmatrix offset pieces
    const int lrA = (lane & 7) + ((lane >> 3) & 1) * 8;  // A / trans-B row part
    const int lcA = ((lane >> 4) & 1) * 8;               // A / trans-B col part
    const int lrK = (lane & 7) + ((lane >> 4) & 1) * 8;  // non-trans B row part
    const int lcK = ((lane >> 3) & 1) * 8;               // non-trans B col part

    // prologue: Q -> qb, K0 -> buf0, K1 -> buf1 (separate groups)
    stage_k(x16b, i_base, qb, tid);            cp_commit();   // Q tile (same layout)
    stage_k(x16b, 0,      sbuf,        tid);   cp_commit();
    stage_k(x16b, TJ,     sbuf + TILE, tid);   cp_commit();

    const int gi0 = i_base + w * 16 + (lane >> 2);
    const int gi1 = gi0 + 8;
    const int jlo0 = (gi0 / KCLS) * KCLS;
    const int jlo1 = (gi1 / KCLS) * KCLS;
    float wr0[4], wr1[4];
    if (gi0 == NKQ) { wr0[0] = wr0[1] = t6[4]; wr0[2] = wr0[3] = t6[5]; }
    else            { wr0[0] = t6[1]; wr0[1] = t6[2]; wr0[2] = t6[0]; wr0[3] = t6[3]; }
    if (gi1 == NKQ) { wr1[0] = wr1[1] = t6[4]; wr1[2] = wr1[3] = t6[5]; }
    else            { wr1[0] = t6[1]; wr1[1] = t6[2]; wr1[2] = t6[0]; wr1[3] = t6[3]; }

    // exact diag scores (fp32 self-dot of x16+xlo); quad lanes split 16 cols each
    float nd0 = 0.f, nd1 = 0.f;
    {
        const int part = lane & 3;
        if (gi0 < L) nd0 = ndot_part(x16b + (size_t)gi0 * D, xlob + (size_t)gi0 * D, part);
        if (gi1 < L) nd1 = ndot_part(x16b + (size_t)gi1 * D, xlob + (size_t)gi1 * D, part);
        nd0 += __shfl_xor_sync(0xffffffffu, nd0, 1);
        nd0 += __shfl_xor_sync(0xffffffffu, nd0, 2);
        nd1 += __shfl_xor_sync(0xffffffffu, nd1, 1);
        nd1 += __shfl_xor_sync(0xffffffffu, nd1, 2);
    }
    // per-row fixed base: exponent_e = (s - nd)/8 - 2  (diag P == e^-2, fp16-normal)
    const float c00 = fmaf(-nd0, C1, EXPB);
    const float c01 = fmaf(-nd1, C1, EXPB);

    cp_wait<2>();            // Q landed
    __syncthreads();

    // hoist fp16 Q A-fragments (16 regs)
    uint32_t qf[4][4];
#pragma unroll
    for (int kc = 0; kc < 4; ++kc) {
        const int off = (w * 16 + lrA) * LDS + kc * 16 + lcA;
        ldmx4(smem_u32(qb + off), qf[kc][0], qf[kc][1], qf[kc][2], qf[kc][3]);
    }

    float o[8][4];
#pragma unroll
    for (int nt = 0; nt < 8; ++nt)
#pragma unroll
        for (int v = 0; v < 4; ++v) o[nt][v] = 0.f;
    float l0 = 0.f, l1 = 0.f;

    const int diag_jt = blockIdx.x;     // TI == TJ: the diagonal falls in this j-tile

    for (int jt = 0; jt < NT; ++jt) {
        const __half* kb = sbuf + (jt & 1) * TILE;   // K(jt)

        cp_wait<1>();        // K(jt) landed; K(jt+1) may be in flight
        __syncthreads();

        float acc[8][4];
        s_phase(kb, qf, acc, lrK, lcK);

        uint32_t ap[4][4];
        float dp0 = 0.f, dp1 = 0.f, pf0 = 0.f, pf1 = 0.f;
        if (jt == NT - 1) {
            if (jt == diag_jt)
                softmax_pack<true , true >(acc, jt * TJ, gi0, gi1, jlo0, jlo1, nd0, nd1,
                                           c00, c01, wr0, wr1, ap, l0, l1, dp0, dp1, pf0, pf1, lane);
            else
                softmax_pack<true , false>(acc, jt * TJ, gi0, gi1, jlo0, jlo1, nd0, nd1,
                                           c00, c01, wr0, wr1, ap, l0, l1, dp0, dp1, pf0, pf1, lane);
        } else {
            if (jt == diag_jt)
                softmax_pack<false, true >(acc, jt * TJ, gi0, gi1, jlo0, jlo1, nd0, nd1,
                                           c00, c01, wr0, wr1, ap, l0, l1, dp0, dp1, pf0, pf1, lane);
            else
                softmax_pack<false, false>(acc, jt * TJ, gi0, gi1, jlo0, jlo1, nd0, nd1,
                                           c00, c01, wr0, wr1, ap, l0, l1, dp0, dp1, pf0, pf1, lane);
        }

        pv_phase(kb, ap, o, lrA, lcA);

        // exact diag correction:
        //   o += (P_diag - fp16(P_diag)) * vhi  +  P_diag * vlo
        // vhi from the smem K tile; vlo read once from global (row gi).
        if (jt == diag_jt) {
            dp0 += __shfl_xor_sync(0xffffffffu, dp0, 1);
            dp0 += __shfl_xor_sync(0xffffffffu, dp0, 2);
            dp1 += __shfl_xor_sync(0xffffffffu, dp1, 1);
            dp1 += __shfl_xor_sync(0xffffffffu, dp1, 2);
            pf0 += __shfl_xor_sync(0xffffffffu, pf0, 1);
            pf0 += __shfl_xor_sync(0xffffffffu, pf0, 2);
            pf1 += __shfl_xor_sync(0xffffffffu, pf1, 1);
            pf1 += __shfl_xor_sync(0xffffffffu, pf1, 2);
            const int lr0 = w * 16 + (lane >> 2);   // local row of gi0 in this tile
            const int lr1 = lr0 + 8;
#pragma unroll
            for (int nt = 0; nt < 8; ++nt) {
                const int c = nt * 8 + (lane & 3) * 2;
                if (gi0 < L) {
                    float2 vh0 = __half22float2(*reinterpret_cast<const __half2*>(kb + lr0 * LDS + c));
                    float2 vl0 = __half22float2(*reinterpret_cast<const __half2*>(xlob + (size_t)gi0 * D + c));
                    o[nt][0] += dp0 * vh0.x + pf0 * vl0.x;
                    o[nt][1] += dp0 * vh0.y + pf0 * vl0.y;
                }
                if (gi1 < L) {
                    float2 vh1 = __half22float2(*reinterpret_cast<const __half2*>(kb + lr1 * LDS + c));
                    float2 vl1 = __half22float2(*reinterpret_cast<const __half2*>(xlob + (size_t)gi1 * D + c));
                    o[nt][2] += dp1 * vh1.x + pf1 * vl1.x;
                    o[nt][3] += dp1 * vh1.y + pf1 * vl1.y;
                }
            }
        }

        __syncthreads();     // all warps done reading kb before restaging it
        if (jt + 2 < NT)
            stage_k(x16b, (jt + 2) * TJ, sbuf + (jt & 1) * TILE, tid);
        cp_commit();         // always commit (possibly empty) to keep wait bookkeeping exact
    }

    // ---- epilogue: reduce denominators once, divide, write ----
    l0 += __shfl_xor_sync(0xffffffffu, l0, 1);
    l0 += __shfl_xor_sync(0xffffffffu, l0, 2);
    l1 += __shfl_xor_sync(0xffffffffu, l1, 1);
    l1 += __shfl_xor_sync(0xffffffffu, l1, 2);
    const float inv0 = 1.f / l0, inv1 = 1.f / l1;

#pragma unroll
    for (int nt = 0; nt < 8; ++nt) {
        const int c = nt * 8 + (lane & 3) * 2;
        if (SPLIT_OUT) {
            if (gi0 < L) {
                uint32_t hi, lo;
                split2h(o[nt][0] * inv0, o[nt][1] * inv0, hi, lo);
                *reinterpret_cast<uint32_t*>(y16 + slice + (size_t)gi0 * D + c) = hi;
                *reinterpret_cast<uint32_t*>(ylo + slice + (size_t)gi0 * D + c) = lo;
            }
            if (gi1 < L) {
                uint32_t hi, lo;
                split2h(o[nt][2] * inv1, o[nt][3] * inv1, hi, lo);
                *reinterpret_cast<uint32_t*>(y16 + slice + (size_t)gi1 * D + c) = hi;
                *reinterpret_cast<uint32_t*>(ylo + slice + (size_t)gi1 * D + c) = lo;
            }
        } else {
            if (gi0 < L)
                *reinterpret_cast<float2*>(yo + slice + (size_t)gi0 * D + c) =
                    make_float2(o[nt][0] * inv0, o[nt][1] * inv0);
            if (gi1 < L)
                *reinterpret_cast<float2*>(yo + slice + (size_t)gi1 * D + c) =
                    make_float2(o[nt][2] * inv1, o[nt][3] * inv1);
        }
    }
}

extern "C" void kernel_launch(void* const* d_in, const int* in_sizes, int n_in,
                              void* d_out, int out_size)
{
    const float* samples = (const float*)d_in[0];   // [B, L, D] fp32
    const float* weights = (const float*)d_in[1];   // [2, H, 6] fp32
    float* out = (float*)d_out;                     // [B, L, D] fp32

    __half *x16, *xlo, *y16, *ylo;
    cudaGetSymbolAddress((void**)&x16, g_x16);
    cudaGetSymbolAddress((void**)&xlo, g_xlo);
    cudaGetSymbolAddress((void**)&y16, g_y16);
    cudaGetSymbolAddress((void**)&ylo, g_ylo);

    cudaFuncSetAttribute(encoder_layer_tc<true >,
                         cudaFuncAttributeMaxDynamicSharedMemorySize, SMEM_BYTES);
    cudaFuncSetAttribute(encoder_layer_tc<false>,
                         cudaFuncAttributeMaxDynamicSharedMemorySize, SMEM_BYTES);

    const int total4 = B * L * D / 4;               // exactly divisible
    convert_split<<<total4 / 256, 256>>>(samples, x16, xlo);

    dim3 grid(NT, B * H);                           // 16 x 128
    encoder_layer_tc<true ><<<grid, 128, SMEM_BYTES>>>(x16, xlo, weights, y16, ylo, nullptr);
    encoder_layer_tc<false><<<grid, 128, SMEM_BYTES>>>(y16, ylo, weights + H * 6,
                                                       nullptr, nullptr, out);
}